// round 10
// baseline (speedup 1.0000x reference)
#include <cuda_runtime.h>
#include <cstdint>

#define NB   16
#define DM   512
#define LSEQ 4096
#define NL   4
#define NS   32

typedef unsigned long long ull;

// ---------------- scratch (device globals; no runtime allocation) ----------------
__device__ float  g_x   [NB * DM * LSEQ];            // layer-0 input (B, D, L)
__device__ float  g_gl  [NB * DM * LSEQ];            // gelu(ssm out) (B, D, L)
__device__ float  g_xp  [NB * DM * LSEQ];            // pre-LN (residual + GLU) (B, D, L)
__device__ float4 g_wc  [NL * DM * NS];              // (w_re, w_im, 2Cc_re, 2Cc_im)
__device__ float  g_proj[NB * DM];
__device__ float  g_posT[DM * LSEQ];
__device__ float  g_mean[NB * LSEQ];                 // LN stats of current xp
__device__ float  g_rstd[NB * LSEQ];

// ---------------- packed f32x2 helpers (exact fp32, 2 FMA/issue) ----------------
__device__ __forceinline__ ull pk2(float lo, float hi) {
    ull r; asm("mov.b64 %0, {%1, %2};" : "=l"(r) : "f"(lo), "f"(hi)); return r;
}
__device__ __forceinline__ void upk2(ull v, float& lo, float& hi) {
    asm("mov.b64 {%0, %1}, %2;" : "=f"(lo), "=f"(hi) : "l"(v));
}
__device__ __forceinline__ ull fma2(ull a, ull b, ull c) {
    ull d; asm("fma.rn.f32x2 %0, %1, %2, %3;" : "=l"(d) : "l"(a), "l"(b), "l"(c)); return d;
}
__device__ __forceinline__ ull mul2(ull a, ull b) {
    ull d; asm("mul.rn.f32x2 %0, %1, %2;" : "=l"(d) : "l"(a), "l"(b)); return d;
}
__device__ __forceinline__ ull add2(ull a, ull b) {
    ull d; asm("add.rn.f32x2 %0, %1, %2;" : "=l"(d) : "l"(a), "l"(b)); return d;
}

// ---------------- precompute discretized SSM params ----------------
__global__ void param_kernel(const float* __restrict__ log_dt,
                             const float* __restrict__ C_re,
                             const float* __restrict__ C_im,
                             const float* __restrict__ lar,
                             const float* __restrict__ aim) {
    int i = blockIdx.x * 256 + threadIdx.x;
    if (i >= NL * DM * NS) return;
    int h     = (i >> 5) & (DM - 1);
    int layer = i >> 14;
    float dt  = expf(log_dt[layer * DM + h]);
    float Are = -expf(lar[i]);
    float Aim = aim[i];
    float er  = expf(dt * Are);
    float wr  = er * cosf(dt * Aim);
    float wi  = er * sinf(dt * Aim);
    float nr  = wr - 1.0f, ni = wi;
    float inv = 1.0f / (Are * Are + Aim * Aim);
    float qr  = (nr * Are + ni * Aim) * inv;
    float qi  = (ni * Are - nr * Aim) * inv;
    float cr  = C_re[i], ci = C_im[i];
    g_wc[i] = make_float4(wr, wi, 2.0f * (cr * qr - ci * qi), 2.0f * (cr * qi + ci * qr));
}

// ---------------- latent projection ----------------
__global__ void proj_kernel(const float* __restrict__ z,
                            const float* __restrict__ Wp,
                            const float* __restrict__ bp) {
    int i = blockIdx.x * 256 + threadIdx.x;          // 8192
    int b = i >> 9, d = i & (DM - 1);
    float s = 0.0f;
    const float* zr = z + b * 256;
    const float* wr = Wp + d * 256;
    #pragma unroll 8
    for (int k = 0; k < 256; k++) s = fmaf(zr[k], wr[k], s);
    g_proj[i] = s + bp[d];
}

// ---------------- transpose pos_emb (L,D) -> (D,L) ----------------
__global__ void transpose_kernel(const float* __restrict__ pe) {
    __shared__ float tile[32][33];
    int l0 = blockIdx.x * 32, d0 = blockIdx.y * 32;
    int tx = threadIdx.x, ty = threadIdx.y;
    #pragma unroll
    for (int r = 0; r < 32; r += 8)
        tile[ty + r][tx] = pe[(size_t)(l0 + ty + r) * DM + d0 + tx];
    __syncthreads();
    #pragma unroll
    for (int r = 0; r < 32; r += 8)
        g_posT[(size_t)(d0 + ty + r) * LSEQ + l0 + tx] = tile[tx][ty + r];
}

// ---------------- x[b,d,l] = proj[b,d] + posT[d,l] ----------------
__global__ void bcast_kernel() {
    int gid = blockIdx.x * 256 + threadIdx.x;
    int idx = gid << 2;
    int l   = idx & (LSEQ - 1);
    int ch  = idx >> 12;
    int d   = ch & (DM - 1);
    float p   = g_proj[ch];
    float4 pv = *(const float4*)&g_posT[(size_t)d * LSEQ + l];
    *(float4*)&g_x[idx] = make_float4(pv.x + p, pv.y + p, pv.z + p, pv.w + p);
}

// ---------------- S4D scan + fused input-LN + D-skip + exact GELU ----------------
__global__ __launch_bounds__(256) void scan_kernel(const float* __restrict__ Dskip_l, int lyr,
                                                   const float* __restrict__ gam_prev,
                                                   const float* __restrict__ bet_prev,
                                                   int first) {
    int warp = (blockIdx.x * 256 + threadIdx.x) >> 5;   // 0..2047
    int lane = threadIdx.x & 31;
    int r    = lane & 7;
    int ch   = warp * 4 + (lane >> 3);                  // b*DM + h
    int h    = ch & (DM - 1);
    int b    = ch >> 9;
    const float4* wc = &g_wc[lyr * (DM * NS) + h * NS + 4 * r];
    float4 p0 = wc[0], p1 = wc[1], p2 = wc[2], p3 = wc[3];
    ull wr2[2]  = { pk2(p0.x, p1.x),   pk2(p2.x, p3.x) };
    ull wi2[2]  = { pk2(p0.y, p1.y),   pk2(p2.y, p3.y) };
    ull nwi2[2] = { pk2(-p0.y, -p1.y), pk2(-p2.y, -p3.y) };
    ull cr2[2]  = { pk2(p0.z, p1.z),   pk2(p2.z, p3.z) };
    ull nci2[2] = { pk2(-p0.w, -p1.w), pk2(-p2.w, -p3.w) };
    float ds = Dskip_l[h];
    float gl = first ? 1.0f : gam_prev[h];
    float bt = first ? 0.0f : bet_prev[h];
    const float* u  = (first ? g_x : g_xp) + (size_t)ch * LSEQ;
    const float* mb = g_mean + (size_t)b * LSEQ;
    const float* rb = g_rstd + (size_t)b * LSEQ;
    float*       go = g_gl + (size_t)ch * LSEQ;
    ull sre2[2] = {0ull, 0ull}, sim2[2] = {0ull, 0ull};
    int src_base = lane & 24;
    for (int l0 = 0; l0 < LSEQ; l0 += 32) {
        float uv[4];
        if (first) {
            #pragma unroll
            for (int q = 0; q < 4; q++) uv[q] = u[l0 + q * 8 + r];      // MLP=4
        } else {
            float vv[4], mm[4], rr[4];
            #pragma unroll
            for (int q = 0; q < 4; q++) {                               // MLP=12
                vv[q] = u [l0 + q * 8 + r];
                mm[q] = mb[l0 + q * 8 + r];
                rr[q] = rb[l0 + q * 8 + r];
            }
            #pragma unroll
            for (int q = 0; q < 4; q++)
                uv[q] = fmaf((vv[q] - mm[q]) * rr[q], gl, bt);          // prev-layer LN
        }
        #pragma unroll
        for (int q = 0; q < 4; q++) {
            ull c2[8];
            #pragma unroll
            for (int j = 0; j < 8; j++) {
                float uj = __shfl_sync(0xffffffffu, uv[q], src_base + j);
                ull uj2 = pk2(uj, uj);
                // pair 0
                ull t0 = fma2(wr2[0], sre2[0], uj2);
                t0     = fma2(nwi2[0], sim2[0], t0);
                ull m0 = mul2(wr2[0], sim2[0]);
                sim2[0] = fma2(wi2[0], sre2[0], m0);
                sre2[0] = t0;
                ull cc0 = fma2(cr2[0], sre2[0], mul2(nci2[0], sim2[0]));
                // pair 1
                ull t1 = fma2(wr2[1], sre2[1], uj2);
                t1     = fma2(nwi2[1], sim2[1], t1);
                ull m1 = mul2(wr2[1], sim2[1]);
                sim2[1] = fma2(wi2[1], sre2[1], m1);
                sre2[1] = t1;
                ull cc1 = fma2(cr2[1], sre2[1], mul2(nci2[1], sim2[1]));
                c2[j] = add2(cc0, cc1);
            }
            // 8-lane transpose-reduce: lane r ends with c2[0] = sum over lanes of c2[r]
            #pragma unroll
            for (int k = 4; k >= 1; k >>= 1) {
                bool hi = (r & k) != 0;
                #pragma unroll
                for (int j = 0; j < k; j++) {
                    ull send = hi ? c2[j]     : c2[j + k];
                    ull keep = hi ? c2[j + k] : c2[j];
                    ull recv = __shfl_xor_sync(0xffffffffu, send, k);
                    c2[j] = add2(keep, recv);
                }
            }
            float lo, hi_;
            upk2(c2[0], lo, hi_);
            float y = lo + hi_;
            y = fmaf(ds, uv[q], y);
            y = 0.5f * y * (1.0f + erff(y * 0.70710678118654752f));
            go[l0 + q * 8 + r] = y;
        }
    }
}

// ---------------- Wconv GEMM + fused GLU + residual(+prev-LN) ----------------
__global__ __launch_bounds__(256) void conv_gemm_glu_kernel(
        const float* __restrict__ A, const float* __restrict__ bias,
        const float* __restrict__ gam_prev, const float* __restrict__ bet_prev,
        int first) {
    __shared__ ull   Ad[2][8][128];       // (a,a) pairs: 16KB
    __shared__ float Bs[2][8][128];       // 8KB
    int tid = threadIdx.x;
    int bN = blockIdx.x;            // 32 L tiles
    int bM = blockIdx.y;            // 8 tiles of 64 d-channels
    int bb = blockIdx.z;            // 16 batches
    const float* Gb = g_gl + (size_t)bb * DM * LSEQ;
    int arow = tid >> 1,  acol = (tid & 1) * 4;
    int grow = (arow < 64) ? (bM * 64 + arow) : (448 + bM * 64 + arow);
    int brow = tid >> 5,  bcol = (tid & 31) * 4;
    int tx = tid & 15,    ty = tid >> 4;
    const float* Ap = A  + (size_t)grow * DM + acol;
    const float* Gp = Gb + (size_t)brow * LSEQ + bN * 128 + bcol;

    ull acc[8][4];
    #pragma unroll
    for (int i = 0; i < 8; i++)
        #pragma unroll
        for (int j = 0; j < 4; j++) acc[i][j] = 0ull;

    // prologue: stage 0
    {
        float4 av = *(const float4*)Ap;
        float4 bv = *(const float4*)Gp;
        Ad[0][acol + 0][arow] = pk2(av.x, av.x);
        Ad[0][acol + 1][arow] = pk2(av.y, av.y);
        Ad[0][acol + 2][arow] = pk2(av.z, av.z);
        Ad[0][acol + 3][arow] = pk2(av.w, av.w);
        *(float4*)&Bs[0][brow][bcol] = bv;
    }
    __syncthreads();

    for (int it = 0; it < 64; it++) {
        const int s = it & 1;
        float4 av, bv;
        if (it < 63) {                           // prefetch tile it+1
            av = *(const float4*)(Ap + (it + 1) * 8);
            bv = *(const float4*)(Gp + (size_t)(it + 1) * 8 * LSEQ);
        }
        #pragma unroll
        for (int k = 0; k < 8; k++) {
            ulonglong2 qa0 = *(const ulonglong2*)&Ad[s][k][ty * 4];        // a-half i=0,1
            ulonglong2 qa1 = *(const ulonglong2*)&Ad[s][k][ty * 4 + 2];    // a-half i=2,3
            ulonglong2 qg0 = *(const ulonglong2*)&Ad[s][k][64 + ty * 4];   // gate i=0,1
            ulonglong2 qg1 = *(const ulonglong2*)&Ad[s][k][64 + ty * 4 + 2];
            ulonglong2 b0 = *(const ulonglong2*)&Bs[s][k][tx * 8];
            ulonglong2 b1 = *(const ulonglong2*)&Bs[s][k][tx * 8 + 4];
            ull bn2[4] = { b0.x, b0.y, b1.x, b1.y };
            ull a2[8]  = { qa0.x, qa0.y, qa1.x, qa1.y, qg0.x, qg0.y, qg1.x, qg1.y };
            #pragma unroll
            for (int i = 0; i < 8; i++)
                #pragma unroll
                for (int j = 0; j < 4; j++) acc[i][j] = fma2(a2[i], bn2[j], acc[i][j]);
        }
        if (it < 63) {
            const int ns = s ^ 1;
            Ad[ns][acol + 0][arow] = pk2(av.x, av.x);
            Ad[ns][acol + 1][arow] = pk2(av.y, av.y);
            Ad[ns][acol + 2][arow] = pk2(av.z, av.z);
            Ad[ns][acol + 3][arow] = pk2(av.w, av.w);
            *(float4*)&Bs[ns][brow][bcol] = bv;
            __syncthreads();
        }
    }
    // epilogue: GLU + residual (+ prev-layer LN), write xp
    int ccol = bN * 128 + tx * 8;
    const float* res = first ? g_x : g_xp;
    const float* mb  = g_mean + (size_t)bb * LSEQ + ccol;
    const float* rb  = g_rstd + (size_t)bb * LSEQ + ccol;
    float mn[8], rs[8];
    if (!first) {
        float4 m0 = *(const float4*)mb, m1 = *(const float4*)(mb + 4);
        float4 r0 = *(const float4*)rb, r1 = *(const float4*)(rb + 4);
        mn[0]=m0.x; mn[1]=m0.y; mn[2]=m0.z; mn[3]=m0.w;
        mn[4]=m1.x; mn[5]=m1.y; mn[6]=m1.z; mn[7]=m1.w;
        rs[0]=r0.x; rs[1]=r0.y; rs[2]=r0.z; rs[3]=r0.w;
        rs[4]=r1.x; rs[5]=r1.y; rs[6]=r1.z; rs[7]=r1.w;
    }
    #pragma unroll
    for (int i = 0; i < 4; i++) {
        int d = bM * 64 + ty * 4 + i;
        float ba = __ldg(&bias[d]);
        float bg = __ldg(&bias[d + 512]);
        float gap = first ? 1.0f : __ldg(&gam_prev[d]);
        float btp = first ? 0.0f : __ldg(&bet_prev[d]);
        float oa[8], og[8];
        #pragma unroll
        for (int j = 0; j < 4; j++) {
            float lo, hi;
            upk2(acc[i][j], lo, hi);
            oa[2 * j] = lo + ba;  oa[2 * j + 1] = hi + ba;
            upk2(acc[i + 4][j], lo, hi);
            og[2 * j] = lo + bg;  og[2 * j + 1] = hi + bg;
        }
        size_t base = ((size_t)bb * DM + d) * LSEQ + ccol;
        float4 x0 = *(const float4*)&res[base];
        float4 x1 = *(const float4*)&res[base + 4];
        float xr[8] = { x0.x, x0.y, x0.z, x0.w, x1.x, x1.y, x1.z, x1.w };
        float o[8];
        #pragma unroll
        for (int j = 0; j < 8; j++) {
            float xv = first ? xr[j] : fmaf((xr[j] - mn[j]) * rs[j], gap, btp);
            float sg = 1.0f / (1.0f + expf(-og[j]));
            o[j] = fmaf(oa[j], sg, xv);
        }
        *(float4*)&g_xp[base]     = make_float4(o[0], o[1], o[2], o[3]);
        *(float4*)&g_xp[base + 4] = make_float4(o[4], o[5], o[6], o[7]);
    }
}

// ---------------- LN stats over xp (deterministic single pass) ----------------
__global__ void ln_stats_kernel() {
    int gid = blockIdx.x * 256 + threadIdx.x;        // 65536
    int b = gid >> 12, l = gid & (LSEQ - 1);
    const float* xp = g_xp + (size_t)b * DM * LSEQ + l;
    float s = 0.0f, s2 = 0.0f;
    #pragma unroll 8
    for (int d = 0; d < DM; d++) {
        float v = __ldg(&xp[(size_t)d * LSEQ]);
        s += v;
        s2 = fmaf(v, v, s2);
    }
    float mean = s * (1.0f / DM);
    float var  = fmaf(-mean, mean, s2 * (1.0f / DM));
    g_mean[gid] = mean;
    g_rstd[gid] = rsqrtf(var + 1e-5f);
}

// ---------------- pixel head (applies final LN inline) ----------------
// Output is the CONCATENATION of two arrays: mu (B,3,H,W) then log_sig (B,3,H,W).
// Channel c<3 -> mu at (b*3+c)*L + l; c>=3 -> log_sig at B*3*L + (b*3+c-3)*L + l.
__global__ void pix_kernel(const float* __restrict__ Wpix,
                           const float* __restrict__ bpix,
                           const float* __restrict__ gam3,
                           const float* __restrict__ bet3,
                           float* __restrict__ out) {
    __shared__ float ws[6 * DM];
    __shared__ float gs[DM];
    __shared__ float bs[DM];
    for (int i = threadIdx.x; i < 6 * DM; i += 256) ws[i] = Wpix[i];
    for (int i = threadIdx.x; i < DM; i += 256) { gs[i] = gam3[i]; bs[i] = bet3[i]; }
    __syncthreads();
    int gid = blockIdx.x * 256 + threadIdx.x;        // 65536
    int b = gid >> 12, l = gid & (LSEQ - 1);
    const float* xb = g_xp + (size_t)b * DM * LSEQ + l;
    float mean = g_mean[gid];
    float rstd = g_rstd[gid];
    float acc[6];
    #pragma unroll
    for (int c = 0; c < 6; c++) acc[c] = __ldg(&bpix[c]);
    #pragma unroll 4
    for (int d = 0; d < DM; d++) {
        float v  = __ldg(&xb[(size_t)d * LSEQ]);
        float xv = fmaf((v - mean) * rstd, gs[d], bs[d]);
        #pragma unroll
        for (int c = 0; c < 6; c++) acc[c] = fmaf(xv, ws[c * DM + d], acc[c]);
    }
    const size_t halfsz = (size_t)NB * 3 * LSEQ;     // 196608
    #pragma unroll
    for (int c = 0; c < 6; c++) {
        size_t idx = (c < 3)
            ? ((size_t)(b * 3 + c) * LSEQ + l)
            : (halfsz + (size_t)(b * 3 + (c - 3)) * LSEQ + l);
        out[idx] = acc[c];
    }
}

// ---------------- launch ----------------
extern "C" void kernel_launch(void* const* d_in, const int* in_sizes, int n_in,
                              void* d_out, int out_size) {
    const float* z      = (const float*)d_in[0];
    const float* Wp     = (const float*)d_in[1];
    const float* bp     = (const float*)d_in[2];
    const float* pe     = (const float*)d_in[3];
    const float* log_dt = (const float*)d_in[4];
    const float* C_re   = (const float*)d_in[5];
    const float* C_im   = (const float*)d_in[6];
    const float* lar    = (const float*)d_in[7];
    const float* aim    = (const float*)d_in[8];
    const float* dsk    = (const float*)d_in[9];
    const float* Wconv  = (const float*)d_in[10];
    const float* bconv  = (const float*)d_in[11];
    const float* gam    = (const float*)d_in[12];
    const float* bet    = (const float*)d_in[13];
    const float* Wpix   = (const float*)d_in[14];
    const float* bpix   = (const float*)d_in[15];
    float* out = (float*)d_out;

    param_kernel<<<256, 256>>>(log_dt, C_re, C_im, lar, aim);
    proj_kernel<<<32, 256>>>(z, Wp, bp);
    transpose_kernel<<<dim3(LSEQ / 32, DM / 32), dim3(32, 8)>>>(pe);
    bcast_kernel<<<32768, 256>>>();

    for (int l = 0; l < NL; l++) {
        const float* gp  = gam + (l > 0 ? (l - 1) : 0) * DM;
        const float* bp2 = bet + (l > 0 ? (l - 1) : 0) * DM;
        scan_kernel<<<256, 256>>>(dsk + l * DM, l, gp, bp2, l == 0);
        conv_gemm_glu_kernel<<<dim3(32, 8, 16), 256>>>(Wconv + (size_t)l * 2 * DM * DM,
                                                       bconv + l * 2 * DM,
                                                       gp, bp2, l == 0);
        ln_stats_kernel<<<256, 256>>>();
    }
    pix_kernel<<<256, 256>>>(Wpix, bpix, gam + 3 * DM, bet + 3 * DM, out);
}

// round 11
// speedup vs baseline: 1.6189x; 1.6189x over previous
#include <cuda_runtime.h>
#include <cuda_bf16.h>
#include <cstdint>

#define NB   16
#define DM   512
#define LSEQ 4096
#define NL   4
#define NS   32

typedef unsigned long long ull;
typedef __nv_bfloat16 bf16;

// ---------------- scratch (device globals; no runtime allocation) ----------------
__device__ float  g_x   [NB * DM * LSEQ];            // layer-0 input (B, D, L)
__device__ float  g_xp  [NB * DM * LSEQ];            // pre-LN (residual + GLU) (B, D, L)
__device__ bf16   g_ghi [NB * DM * LSEQ];            // gelu out (B, D, L), bf16 hi
__device__ bf16   g_glo [NB * DM * LSEQ];            // bf16 lo
__device__ bf16   g_whi [NL * 2 * DM * DM];          // Wconv split hi (layer, 2D, D)
__device__ bf16   g_wlo [NL * 2 * DM * DM];          // lo
__device__ float4 g_wc  [NL * DM * NS];              // (w_re, w_im, 2Cc_re, 2Cc_im)
__device__ float  g_proj[NB * DM];
__device__ float  g_posT[DM * LSEQ];
__device__ float  g_mean[NB * LSEQ];                 // LN stats of current xp
__device__ float  g_rstd[NB * LSEQ];

// ---------------- helpers ----------------
__device__ __forceinline__ uint32_t smem_u32(const void* p) {
    uint32_t a;
    asm("{ .reg .u64 t; cvta.to.shared.u64 t, %1; cvt.u32.u64 %0, t; }" : "=r"(a) : "l"(p));
    return a;
}
__device__ __forceinline__ void cpasync16(uint32_t dst, const void* src) {
    asm volatile("cp.async.cg.shared.global [%0], [%1], 16;" :: "r"(dst), "l"(src) : "memory");
}
__device__ __forceinline__ void ldsm4(uint32_t (&r)[4], uint32_t addr) {
    asm volatile("ldmatrix.sync.aligned.m8n8.x4.shared.b16 {%0,%1,%2,%3}, [%4];"
                 : "=r"(r[0]), "=r"(r[1]), "=r"(r[2]), "=r"(r[3]) : "r"(addr));
}
__device__ __forceinline__ void ldsm4t(uint32_t (&r)[4], uint32_t addr) {
    asm volatile("ldmatrix.sync.aligned.m8n8.x4.trans.shared.b16 {%0,%1,%2,%3}, [%4];"
                 : "=r"(r[0]), "=r"(r[1]), "=r"(r[2]), "=r"(r[3]) : "r"(addr));
}
__device__ __forceinline__ void mma16816(float (&c)[4], const uint32_t (&a)[4],
                                         uint32_t b0, uint32_t b1) {
    asm volatile("mma.sync.aligned.m16n8k16.row.col.f32.bf16.bf16.f32 "
                 "{%0,%1,%2,%3}, {%4,%5,%6,%7}, {%8,%9}, {%0,%1,%2,%3};"
                 : "+f"(c[0]), "+f"(c[1]), "+f"(c[2]), "+f"(c[3])
                 : "r"(a[0]), "r"(a[1]), "r"(a[2]), "r"(a[3]), "r"(b0), "r"(b1));
}
// packed f32x2 (exact fp32, 2 FMA/issue) — used by the scan
__device__ __forceinline__ ull pk2(float lo, float hi) {
    ull r; asm("mov.b64 %0, {%1, %2};" : "=l"(r) : "f"(lo), "f"(hi)); return r;
}
__device__ __forceinline__ void upk2(ull v, float& lo, float& hi) {
    asm("mov.b64 {%0, %1}, %2;" : "=f"(lo), "=f"(hi) : "l"(v));
}
__device__ __forceinline__ ull fma2(ull a, ull b, ull c) {
    ull d; asm("fma.rn.f32x2 %0, %1, %2, %3;" : "=l"(d) : "l"(a), "l"(b), "l"(c)); return d;
}
__device__ __forceinline__ ull mul2(ull a, ull b) {
    ull d; asm("mul.rn.f32x2 %0, %1, %2;" : "=l"(d) : "l"(a), "l"(b)); return d;
}
__device__ __forceinline__ ull add2(ull a, ull b) {
    ull d; asm("add.rn.f32x2 %0, %1, %2;" : "=l"(d) : "l"(a), "l"(b)); return d;
}

// ---------------- precompute discretized SSM params ----------------
__global__ void param_kernel(const float* __restrict__ log_dt,
                             const float* __restrict__ C_re,
                             const float* __restrict__ C_im,
                             const float* __restrict__ lar,
                             const float* __restrict__ aim) {
    int i = blockIdx.x * 256 + threadIdx.x;
    if (i >= NL * DM * NS) return;
    int h     = (i >> 5) & (DM - 1);
    int layer = i >> 14;
    float dt  = expf(log_dt[layer * DM + h]);
    float Are = -expf(lar[i]);
    float Aim = aim[i];
    float er  = expf(dt * Are);
    float wr  = er * cosf(dt * Aim);
    float wi  = er * sinf(dt * Aim);
    float nr  = wr - 1.0f, ni = wi;
    float inv = 1.0f / (Are * Are + Aim * Aim);
    float qr  = (nr * Are + ni * Aim) * inv;
    float qi  = (ni * Are - nr * Aim) * inv;
    float cr  = C_re[i], ci = C_im[i];
    g_wc[i] = make_float4(wr, wi, 2.0f * (cr * qr - ci * qi), 2.0f * (cr * qi + ci * qr));
}

// ---------------- W split into bf16 hi/lo ----------------
__global__ void wsplit_kernel(const float* __restrict__ W) {
    int i = blockIdx.x * 256 + threadIdx.x;          // NL*2D*D = 2,097,152
    if (i >= NL * 2 * DM * DM) return;
    float w = W[i];
    bf16 hi = __float2bfloat16_rn(w);
    g_whi[i] = hi;
    g_wlo[i] = __float2bfloat16_rn(w - __bfloat162float(hi));
}

// ---------------- latent projection ----------------
__global__ void proj_kernel(const float* __restrict__ z,
                            const float* __restrict__ Wp,
                            const float* __restrict__ bp) {
    int i = blockIdx.x * 256 + threadIdx.x;          // 8192
    int b = i >> 9, d = i & (DM - 1);
    float s = 0.0f;
    const float* zr = z + b * 256;
    const float* wr = Wp + d * 256;
    #pragma unroll 8
    for (int k = 0; k < 256; k++) s = fmaf(zr[k], wr[k], s);
    g_proj[i] = s + bp[d];
}

// ---------------- transpose pos_emb (L,D) -> (D,L) ----------------
__global__ void transpose_kernel(const float* __restrict__ pe) {
    __shared__ float tile[32][33];
    int l0 = blockIdx.x * 32, d0 = blockIdx.y * 32;
    int tx = threadIdx.x, ty = threadIdx.y;
    #pragma unroll
    for (int r = 0; r < 32; r += 8)
        tile[ty + r][tx] = pe[(size_t)(l0 + ty + r) * DM + d0 + tx];
    __syncthreads();
    #pragma unroll
    for (int r = 0; r < 32; r += 8)
        g_posT[(size_t)(d0 + ty + r) * LSEQ + l0 + tx] = tile[tx][ty + r];
}

// ---------------- x[b,d,l] = proj[b,d] + posT[d,l] ----------------
__global__ void bcast_kernel() {
    int gid = blockIdx.x * 256 + threadIdx.x;
    int idx = gid << 2;
    int l   = idx & (LSEQ - 1);
    int ch  = idx >> 12;
    int d   = ch & (DM - 1);
    float p   = g_proj[ch];
    float4 pv = *(const float4*)&g_posT[(size_t)d * LSEQ + l];
    *(float4*)&g_x[idx] = make_float4(pv.x + p, pv.y + p, pv.z + p, pv.w + p);
}

// ---------------- S4D scan + fused input-LN + D-skip + exact GELU -> bf16 hi/lo ----------------
__global__ __launch_bounds__(256) void scan_kernel(const float* __restrict__ Dskip_l, int lyr,
                                                   const float* __restrict__ gam_prev,
                                                   const float* __restrict__ bet_prev,
                                                   int first) {
    int warp = (blockIdx.x * 256 + threadIdx.x) >> 5;   // 0..2047
    int lane = threadIdx.x & 31;
    int r    = lane & 7;
    int ch   = warp * 4 + (lane >> 3);                  // b*DM + h
    int h    = ch & (DM - 1);
    int b    = ch >> 9;
    const float4* wc = &g_wc[lyr * (DM * NS) + h * NS + 4 * r];
    float4 p0 = wc[0], p1 = wc[1], p2 = wc[2], p3 = wc[3];
    ull wr2[2]  = { pk2(p0.x, p1.x),   pk2(p2.x, p3.x) };
    ull wi2[2]  = { pk2(p0.y, p1.y),   pk2(p2.y, p3.y) };
    ull nwi2[2] = { pk2(-p0.y, -p1.y), pk2(-p2.y, -p3.y) };
    ull cr2[2]  = { pk2(p0.z, p1.z),   pk2(p2.z, p3.z) };
    ull nci2[2] = { pk2(-p0.w, -p1.w), pk2(-p2.w, -p3.w) };
    float ds = Dskip_l[h];
    float gl = first ? 1.0f : gam_prev[h];
    float bt = first ? 0.0f : bet_prev[h];
    const float* u  = (first ? g_x : g_xp) + (size_t)ch * LSEQ;
    const float* mb = g_mean + (size_t)b * LSEQ;
    const float* rb = g_rstd + (size_t)b * LSEQ;
    bf16* ghi = g_ghi + (size_t)ch * LSEQ;
    bf16* glo = g_glo + (size_t)ch * LSEQ;
    ull sre2[2] = {0ull, 0ull}, sim2[2] = {0ull, 0ull};
    int src_base = lane & 24;
    for (int l0 = 0; l0 < LSEQ; l0 += 32) {
        float uv[4];
        if (first) {
            #pragma unroll
            for (int q = 0; q < 4; q++) uv[q] = u[l0 + q * 8 + r];      // MLP=4
        } else {
            float vv[4], mm[4], rr[4];
            #pragma unroll
            for (int q = 0; q < 4; q++) {                               // MLP=12
                vv[q] = u [l0 + q * 8 + r];
                mm[q] = mb[l0 + q * 8 + r];
                rr[q] = rb[l0 + q * 8 + r];
            }
            #pragma unroll
            for (int q = 0; q < 4; q++)
                uv[q] = fmaf((vv[q] - mm[q]) * rr[q], gl, bt);          // prev-layer LN
        }
        #pragma unroll
        for (int q = 0; q < 4; q++) {
            ull c2[8];
            #pragma unroll
            for (int j = 0; j < 8; j++) {
                float uj = __shfl_sync(0xffffffffu, uv[q], src_base + j);
                ull uj2 = pk2(uj, uj);
                ull t0 = fma2(wr2[0], sre2[0], uj2);
                t0     = fma2(nwi2[0], sim2[0], t0);
                ull m0 = mul2(wr2[0], sim2[0]);
                sim2[0] = fma2(wi2[0], sre2[0], m0);
                sre2[0] = t0;
                ull cc0 = fma2(cr2[0], sre2[0], mul2(nci2[0], sim2[0]));
                ull t1 = fma2(wr2[1], sre2[1], uj2);
                t1     = fma2(nwi2[1], sim2[1], t1);
                ull m1 = mul2(wr2[1], sim2[1]);
                sim2[1] = fma2(wi2[1], sre2[1], m1);
                sre2[1] = t1;
                ull cc1 = fma2(cr2[1], sre2[1], mul2(nci2[1], sim2[1]));
                c2[j] = add2(cc0, cc1);
            }
            #pragma unroll
            for (int k = 4; k >= 1; k >>= 1) {
                bool hiq = (r & k) != 0;
                #pragma unroll
                for (int j = 0; j < k; j++) {
                    ull send = hiq ? c2[j]     : c2[j + k];
                    ull keep = hiq ? c2[j + k] : c2[j];
                    ull recv = __shfl_xor_sync(0xffffffffu, send, k);
                    c2[j] = add2(keep, recv);
                }
            }
            float lo_, hi_;
            upk2(c2[0], lo_, hi_);
            float y = lo_ + hi_;
            y = fmaf(ds, uv[q], y);
            y = 0.5f * y * (1.0f + erff(y * 0.70710678118654752f));
            bf16 yh = __float2bfloat16_rn(y);
            ghi[l0 + q * 8 + r] = yh;
            glo[l0 + q * 8 + r] = __float2bfloat16_rn(y - __bfloat162float(yh));
        }
    }
}

// ---------------- mma.sync bf16-split GEMM + fused GLU + residual(+prev-LN) ----------------
// One logical GEMM with K' = 1536: kt 0-7 Whi*Ghi, 8-15 Whi*Glo, 16-23 Wlo*Ghi.
// CTA tile: M=128 (rows 0-63 = a-channels d, 64-127 = gate channels d+512), N=128, BK=64.
// Warp (wy 0-3, wx 0-1): a-strip m16 at wy*16, gate-strip at 64+wy*16, n64 at wx*64.
// cp.async double buffer (2 x 32KB), XOR-swizzled smem, ldmatrix A / ldmatrix.trans B.
__global__ __launch_bounds__(256, 2) void gemm_mma_kernel(
        const bf16* __restrict__ whi, const bf16* __restrict__ wlo,
        const float* __restrict__ bias,
        const float* __restrict__ gam_prev, const float* __restrict__ bet_prev,
        int first) {
    extern __shared__ char smem[];
    const uint32_t sb = smem_u32(smem);
    const int tid = threadIdx.x;
    const int warp = tid >> 5, lane = tid & 31;
    const int wy = warp & 3, wx = warp >> 2;
    const int bN = blockIdx.x, bM = blockIdx.y, bb = blockIdx.z;
    const bf16* ghi = g_ghi + (size_t)bb * DM * LSEQ;
    const bf16* glo = g_glo + (size_t)bb * DM * LSEQ;

    float c[2][8][4];
    #pragma unroll
    for (int st = 0; st < 2; st++)
        #pragma unroll
        for (int nt = 0; nt < 8; nt++)
            #pragma unroll
            for (int j = 0; j < 4; j++) c[st][nt][j] = 0.0f;

    // ---- cp.async stage issue ----
    auto issue = [&](int kt, int s) {
        const bf16* Wsrc = (kt < 16) ? whi : wlo;
        const bf16* Gsrc = (kt >= 8 && kt < 16) ? glo : ghi;
        const int k0 = (kt & 7) * 64;
        const uint32_t As  = sb + s * 32768;
        const uint32_t Bsm = As + 16384;
        #pragma unroll
        for (int i = 0; i < 4; i++) {
            int ca = i * 256 + tid;                    // A: 1024 chunks (128m x 8)
            int m = ca >> 3, kc = ca & 7;
            int grow = (m < 64) ? (bM * 64 + m) : (448 + bM * 64 + m);
            cpasync16(As + m * 128 + ((kc ^ (m & 7)) << 4),
                      Wsrc + (size_t)grow * DM + k0 + kc * 8);
            int k = ca >> 4, cn = ca & 15;             // B: 1024 chunks (64k x 16)
            uint32_t cns = (cn & 8) | ((cn ^ (k & 7)) & 7);
            cpasync16(Bsm + k * 256 + (cns << 4),
                      Gsrc + (size_t)(k0 + k) * LSEQ + bN * 128 + cn * 8);
        }
        asm volatile("cp.async.commit_group;" ::: "memory");
    };

    issue(0, 0);
    const int q  = lane >> 3, r = lane & 7;
    const int qm = q & 1,  qh = q >> 1;
    const uint32_t aoff0 = (wy * 16 + qm * 8 + r) * 128;
    const uint32_t aoff1 = (64 + wy * 16 + qm * 8 + r) * 128;
    const uint32_t kboff = (qm * 8 + r) * 256;

    for (int kt = 0; kt < 24; kt++) {
        const int s = kt & 1;
        asm volatile("cp.async.wait_group 0;" ::: "memory");
        __syncthreads();
        if (kt < 23) issue(kt + 1, s ^ 1);
        const uint32_t As  = sb + s * 32768;
        const uint32_t Bsm = As + 16384;
        #pragma unroll
        for (int kk = 0; kk < 4; kk++) {
            uint32_t ac = (uint32_t)(((kk * 2 + qh) ^ r) << 4);
            uint32_t a0[4], a1[4];
            ldsm4(a0, As + aoff0 + ac);
            ldsm4(a1, As + aoff1 + ac);
            uint32_t bfr[4][4];
            uint32_t krow = Bsm + kboff + kk * 16 * 256;
            #pragma unroll
            for (int pt = 0; pt < 4; pt++) {
                uint32_t cn  = wx * 8 + pt * 2 + qh;
                uint32_t cns = (cn & 8) | ((cn ^ r) & 7);
                ldsm4t(bfr[pt], krow + (cns << 4));
            }
            #pragma unroll
            for (int nt = 0; nt < 8; nt++) {
                uint32_t b0 = bfr[nt >> 1][(nt & 1) * 2];
                uint32_t b1 = bfr[nt >> 1][(nt & 1) * 2 + 1];
                mma16816(c[0][nt], a0, b0, b1);
                mma16816(c[1][nt], a1, b0, b1);
            }
        }
    }

    // ---- epilogue: GLU + residual (+ prev-layer LN), registers only ----
    const int gi = lane >> 2, tig = lane & 3;
    const float* res = first ? g_x : g_xp;
    const float* mb  = g_mean + (size_t)bb * LSEQ;
    const float* rb  = g_rstd + (size_t)bb * LSEQ;
    #pragma unroll
    for (int rr = 0; rr < 2; rr++) {                  // rows gi and gi+8
        int d = bM * 64 + wy * 16 + gi + rr * 8;
        float ba = bias[d];
        float bg = bias[512 + d];
        float gap = first ? 1.0f : gam_prev[d];
        float btp = first ? 0.0f : bet_prev[d];
        size_t rowbase = ((size_t)bb * DM + d) * LSEQ;
        #pragma unroll
        for (int nt = 0; nt < 8; nt++) {
            int l = bN * 128 + wx * 64 + nt * 8 + 2 * tig;
            float av0 = c[0][nt][rr * 2]     + ba;
            float av1 = c[0][nt][rr * 2 + 1] + ba;
            float gv0 = c[1][nt][rr * 2]     + bg;
            float gv1 = c[1][nt][rr * 2 + 1] + bg;
            float2 xr = *(const float2*)&res[rowbase + l];
            float x0, x1;
            if (first) { x0 = xr.x; x1 = xr.y; }
            else {
                float2 mn = *(const float2*)&mb[l];
                float2 rs = *(const float2*)&rb[l];
                x0 = fmaf((xr.x - mn.x) * rs.x, gap, btp);
                x1 = fmaf((xr.y - mn.y) * rs.y, gap, btp);
            }
            float o0 = fmaf(av0, 1.0f / (1.0f + expf(-gv0)), x0);
            float o1 = fmaf(av1, 1.0f / (1.0f + expf(-gv1)), x1);
            *(float2*)&g_xp[rowbase + l] = make_float2(o0, o1);
        }
    }
}

// ---------------- LN stats over xp (deterministic single pass) ----------------
__global__ void ln_stats_kernel() {
    int gid = blockIdx.x * 256 + threadIdx.x;        // 65536
    int b = gid >> 12, l = gid & (LSEQ - 1);
    const float* xp = g_xp + (size_t)b * DM * LSEQ + l;
    float s = 0.0f, s2 = 0.0f;
    #pragma unroll 8
    for (int d = 0; d < DM; d++) {
        float v = __ldg(&xp[(size_t)d * LSEQ]);
        s += v;
        s2 = fmaf(v, v, s2);
    }
    float mean = s * (1.0f / DM);
    float var  = fmaf(-mean, mean, s2 * (1.0f / DM));
    g_mean[gid] = mean;
    g_rstd[gid] = rsqrtf(var + 1e-5f);
}

// ---------------- pixel head (applies final LN inline) ----------------
// Output = concat(mu (B,3,H,W), log_sig (B,3,H,W)).
__global__ void pix_kernel(const float* __restrict__ Wpix,
                           const float* __restrict__ bpix,
                           const float* __restrict__ gam3,
                           const float* __restrict__ bet3,
                           float* __restrict__ out) {
    __shared__ float ws[6 * DM];
    __shared__ float gs[DM];
    __shared__ float bs[DM];
    for (int i = threadIdx.x; i < 6 * DM; i += 256) ws[i] = Wpix[i];
    for (int i = threadIdx.x; i < DM; i += 256) { gs[i] = gam3[i]; bs[i] = bet3[i]; }
    __syncthreads();
    int gid = blockIdx.x * 256 + threadIdx.x;        // 65536
    int b = gid >> 12, l = gid & (LSEQ - 1);
    const float* xb = g_xp + (size_t)b * DM * LSEQ + l;
    float mean = g_mean[gid];
    float rstd = g_rstd[gid];
    float acc[6];
    #pragma unroll
    for (int c = 0; c < 6; c++) acc[c] = __ldg(&bpix[c]);
    #pragma unroll 4
    for (int d = 0; d < DM; d++) {
        float v  = __ldg(&xb[(size_t)d * LSEQ]);
        float xv = fmaf((v - mean) * rstd, gs[d], bs[d]);
        #pragma unroll
        for (int c = 0; c < 6; c++) acc[c] = fmaf(xv, ws[c * DM + d], acc[c]);
    }
    const size_t halfsz = (size_t)NB * 3 * LSEQ;     // 196608
    #pragma unroll
    for (int c = 0; c < 6; c++) {
        size_t idx = (c < 3)
            ? ((size_t)(b * 3 + c) * LSEQ + l)
            : (halfsz + (size_t)(b * 3 + (c - 3)) * LSEQ + l);
        out[idx] = acc[c];
    }
}

// ---------------- launch ----------------
extern "C" void kernel_launch(void* const* d_in, const int* in_sizes, int n_in,
                              void* d_out, int out_size) {
    const float* z      = (const float*)d_in[0];
    const float* Wp     = (const float*)d_in[1];
    const float* bp     = (const float*)d_in[2];
    const float* pe     = (const float*)d_in[3];
    const float* log_dt = (const float*)d_in[4];
    const float* C_re   = (const float*)d_in[5];
    const float* C_im   = (const float*)d_in[6];
    const float* lar    = (const float*)d_in[7];
    const float* aim    = (const float*)d_in[8];
    const float* dsk    = (const float*)d_in[9];
    const float* Wconv  = (const float*)d_in[10];
    const float* bconv  = (const float*)d_in[11];
    const float* gam    = (const float*)d_in[12];
    const float* bet    = (const float*)d_in[13];
    const float* Wpix   = (const float*)d_in[14];
    const float* bpix   = (const float*)d_in[15];
    float* out = (float*)d_out;

    cudaFuncSetAttribute(gemm_mma_kernel, cudaFuncAttributeMaxDynamicSharedMemorySize, 65536);

    param_kernel<<<256, 256>>>(log_dt, C_re, C_im, lar, aim);
    wsplit_kernel<<<8192, 256>>>(Wconv);
    proj_kernel<<<32, 256>>>(z, Wp, bp);
    transpose_kernel<<<dim3(LSEQ / 32, DM / 32), dim3(32, 8)>>>(pe);
    bcast_kernel<<<32768, 256>>>();

    bf16* whi; cudaGetSymbolAddress((void**)&whi, g_whi);
    bf16* wlo; cudaGetSymbolAddress((void**)&wlo, g_wlo);

    for (int l = 0; l < NL; l++) {
        const float* gp  = gam + (l > 0 ? (l - 1) : 0) * DM;
        const float* bp2 = bet + (l > 0 ? (l - 1) : 0) * DM;
        scan_kernel<<<256, 256>>>(dsk + l * DM, l, gp, bp2, l == 0);
        gemm_mma_kernel<<<dim3(32, 8, 16), 256, 65536>>>(
            whi + (size_t)l * 2 * DM * DM, wlo + (size_t)l * 2 * DM * DM,
            bconv + l * 2 * DM, gp, bp2, l == 0);
        ln_stats_kernel<<<256, 256>>>();
    }
    pix_kernel<<<256, 256>>>(Wpix, bpix, gam + 3 * DM, bet + 3 * DM, out);
}

// round 13
// speedup vs baseline: 1.6408x; 1.0135x over previous
#include <cuda_runtime.h>
#include <cuda_bf16.h>
#include <cstdint>

#define NB   16
#define DM   512
#define LSEQ 4096
#define NL   4
#define NS   32

typedef unsigned long long ull;
typedef __nv_bfloat16 bf16;

// ---------------- scratch (device globals; no runtime allocation) ----------------
__device__ float  g_xp  [NB * DM * LSEQ];            // pre-LN (residual + GLU) (B, D, L)
__device__ bf16   g_ghi [NB * DM * LSEQ];            // gelu out (B, D, L), bf16 hi
__device__ bf16   g_glo [NB * DM * LSEQ];            // bf16 lo
__device__ bf16   g_whi [NL * 2 * DM * DM];          // Wconv split hi (layer, 2D, D)
__device__ bf16   g_wlo [NL * 2 * DM * DM];          // lo
__device__ float4 g_wc  [NL * DM * NS];              // (w_re, w_im, 2Cc_re, 2Cc_im)
__device__ float  g_proj[NB * DM];
__device__ float  g_posT[DM * LSEQ];
__device__ float  g_mean[NB * LSEQ];                 // LN stats of current xp
__device__ float  g_rstd[NB * LSEQ];

// ---------------- helpers ----------------
__device__ __forceinline__ uint32_t smem_u32(const void* p) {
    uint32_t a;
    asm("{ .reg .u64 t; cvta.to.shared.u64 t, %1; cvt.u32.u64 %0, t; }" : "=r"(a) : "l"(p));
    return a;
}
__device__ __forceinline__ void cpasync16(uint32_t dst, const void* src) {
    asm volatile("cp.async.cg.shared.global [%0], [%1], 16;" :: "r"(dst), "l"(src) : "memory");
}
__device__ __forceinline__ void ldsm4(uint32_t (&r)[4], uint32_t addr) {
    asm volatile("ldmatrix.sync.aligned.m8n8.x4.shared.b16 {%0,%1,%2,%3}, [%4];"
                 : "=r"(r[0]), "=r"(r[1]), "=r"(r[2]), "=r"(r[3]) : "r"(addr));
}
__device__ __forceinline__ void ldsm4t(uint32_t (&r)[4], uint32_t addr) {
    asm volatile("ldmatrix.sync.aligned.m8n8.x4.trans.shared.b16 {%0,%1,%2,%3}, [%4];"
                 : "=r"(r[0]), "=r"(r[1]), "=r"(r[2]), "=r"(r[3]) : "r"(addr));
}
__device__ __forceinline__ void mma16816(float (&c)[4], const uint32_t (&a)[4],
                                         uint32_t b0, uint32_t b1) {
    asm volatile("mma.sync.aligned.m16n8k16.row.col.f32.bf16.bf16.f32 "
                 "{%0,%1,%2,%3}, {%4,%5,%6,%7}, {%8,%9}, {%0,%1,%2,%3};"
                 : "+f"(c[0]), "+f"(c[1]), "+f"(c[2]), "+f"(c[3])
                 : "r"(a[0]), "r"(a[1]), "r"(a[2]), "r"(a[3]), "r"(b0), "r"(b1));
}
// packed f32x2 (exact fp32, 2 FMA/issue) — used by the scan
__device__ __forceinline__ ull pk2(float lo, float hi) {
    ull r; asm("mov.b64 %0, {%1, %2};" : "=l"(r) : "f"(lo), "f"(hi)); return r;
}
__device__ __forceinline__ void upk2(ull v, float& lo, float& hi) {
    asm("mov.b64 {%0, %1}, %2;" : "=f"(lo), "=f"(hi) : "l"(v));
}
__device__ __forceinline__ ull fma2(ull a, ull b, ull c) {
    ull d; asm("fma.rn.f32x2 %0, %1, %2, %3;" : "=l"(d) : "l"(a), "l"(b), "l"(c)); return d;
}
__device__ __forceinline__ ull mul2(ull a, ull b) {
    ull d; asm("mul.rn.f32x2 %0, %1, %2;" : "=l"(d) : "l"(a), "l"(b)); return d;
}
__device__ __forceinline__ ull add2(ull a, ull b) {
    ull d; asm("add.rn.f32x2 %0, %1, %2;" : "=l"(d) : "l"(a), "l"(b)); return d;
}

// ---------------- initA: SSM params + W bf16 hi/lo split (one launch) ----------------
__global__ void initA_kernel(const float* __restrict__ log_dt,
                             const float* __restrict__ C_re,
                             const float* __restrict__ C_im,
                             const float* __restrict__ lar,
                             const float* __restrict__ aim,
                             const float* __restrict__ W) {
    int i = blockIdx.x * 256 + threadIdx.x;          // 2,097,152 threads
    if (i < NL * 2 * DM * DM) {
        float w = W[i];
        bf16 hi = __float2bfloat16_rn(w);
        g_whi[i] = hi;
        g_wlo[i] = __float2bfloat16_rn(w - __bfloat162float(hi));
    }
    if (i < NL * DM * NS) {
        int h     = (i >> 5) & (DM - 1);
        int layer = i >> 14;
        float dt  = expf(log_dt[layer * DM + h]);
        float Are = -expf(lar[i]);
        float Aim = aim[i];
        float er  = expf(dt * Are);
        float wr  = er * cosf(dt * Aim);
        float wi  = er * sinf(dt * Aim);
        float nr  = wr - 1.0f, ni = wi;
        float inv = 1.0f / (Are * Are + Aim * Aim);
        float qr  = (nr * Are + ni * Aim) * inv;
        float qi  = (ni * Are - nr * Aim) * inv;
        float cr  = C_re[i], ci = C_im[i];
        g_wc[i] = make_float4(wr, wi, 2.0f * (cr * qr - ci * qi), 2.0f * (cr * qi + ci * qr));
    }
}

// ---------------- initB: pos transpose (blocks 0..2047) + latent proj (blocks 2048..2079) ---
__global__ void initB_kernel(const float* __restrict__ pe,
                             const float* __restrict__ z,
                             const float* __restrict__ Wp,
                             const float* __restrict__ bp) {
    int blk = blockIdx.x;
    if (blk < 2048) {
        __shared__ float tile[32][33];
        int l0 = (blk & 127) * 32, d0 = (blk >> 7) * 32;
        int tx = threadIdx.x & 31, ty = threadIdx.x >> 5;
        #pragma unroll
        for (int r = 0; r < 32; r += 8)
            tile[ty + r][tx] = pe[(size_t)(l0 + ty + r) * DM + d0 + tx];
        __syncthreads();
        #pragma unroll
        for (int r = 0; r < 32; r += 8)
            g_posT[(size_t)(d0 + ty + r) * LSEQ + l0 + tx] = tile[tx][ty + r];
    } else {
        int i = (blk - 2048) * 256 + threadIdx.x;    // 8192
        int b = i >> 9, d = i & (DM - 1);
        float s = 0.0f;
        const float* zr = z + b * 256;
        const float* wr = Wp + d * 256;
        #pragma unroll 8
        for (int k = 0; k < 256; k++) s = fmaf(zr[k], wr[k], s);
        g_proj[i] = s + bp[d];
    }
}

// ---------------- S4D scan + fused input (layer0: proj+pos; else LN(xp)) + GELU -> bf16 ----
__global__ __launch_bounds__(256) void scan_kernel(const float* __restrict__ Dskip_l, int lyr,
                                                   const float* __restrict__ gam_prev,
                                                   const float* __restrict__ bet_prev,
                                                   int first) {
    int warp = (blockIdx.x * 256 + threadIdx.x) >> 5;   // 0..2047
    int lane = threadIdx.x & 31;
    int r    = lane & 7;
    int ch   = warp * 4 + (lane >> 3);                  // b*DM + h
    int h    = ch & (DM - 1);
    int b    = ch >> 9;
    const float4* wc = &g_wc[lyr * (DM * NS) + h * NS + 4 * r];
    float4 p0 = wc[0], p1 = wc[1], p2 = wc[2], p3 = wc[3];
    ull wr2[2]  = { pk2(p0.x, p1.x),   pk2(p2.x, p3.x) };
    ull wi2[2]  = { pk2(p0.y, p1.y),   pk2(p2.y, p3.y) };
    ull nwi2[2] = { pk2(-p0.y, -p1.y), pk2(-p2.y, -p3.y) };
    ull cr2[2]  = { pk2(p0.z, p1.z),   pk2(p2.z, p3.z) };
    ull nci2[2] = { pk2(-p0.w, -p1.w), pk2(-p2.w, -p3.w) };
    float ds = Dskip_l[h];
    float gl = first ? 1.0f : gam_prev[h];
    float bt = first ? 0.0f : bet_prev[h];
    float pv = first ? g_proj[ch] : 0.0f;
    const float* u  = first ? (g_posT + (size_t)h * LSEQ) : (g_xp + (size_t)ch * LSEQ);
    const float* mb = g_mean + (size_t)b * LSEQ;
    const float* rb = g_rstd + (size_t)b * LSEQ;
    bf16* ghi = g_ghi + (size_t)ch * LSEQ;
    bf16* glo = g_glo + (size_t)ch * LSEQ;
    ull sre2[2] = {0ull, 0ull}, sim2[2] = {0ull, 0ull};
    int src_base = lane & 24;
    for (int l0 = 0; l0 < LSEQ; l0 += 32) {
        float uv[4];
        if (first) {
            #pragma unroll
            for (int q = 0; q < 4; q++) uv[q] = u[l0 + q * 8 + r] + pv;  // proj + pos
        } else {
            float vv[4], mm[4], rr[4];
            #pragma unroll
            for (int q = 0; q < 4; q++) {                               // MLP=12
                vv[q] = u [l0 + q * 8 + r];
                mm[q] = mb[l0 + q * 8 + r];
                rr[q] = rb[l0 + q * 8 + r];
            }
            #pragma unroll
            for (int q = 0; q < 4; q++)
                uv[q] = fmaf((vv[q] - mm[q]) * rr[q], gl, bt);          // prev-layer LN
        }
        #pragma unroll
        for (int q = 0; q < 4; q++) {
            ull c2[8];
            #pragma unroll
            for (int j = 0; j < 8; j++) {
                float uj = __shfl_sync(0xffffffffu, uv[q], src_base + j);
                ull uj2 = pk2(uj, uj);
                ull t0 = fma2(wr2[0], sre2[0], uj2);
                t0     = fma2(nwi2[0], sim2[0], t0);
                ull m0 = mul2(wr2[0], sim2[0]);
                sim2[0] = fma2(wi2[0], sre2[0], m0);
                sre2[0] = t0;
                ull cc0 = fma2(cr2[0], sre2[0], mul2(nci2[0], sim2[0]));
                ull t1 = fma2(wr2[1], sre2[1], uj2);
                t1     = fma2(nwi2[1], sim2[1], t1);
                ull m1 = mul2(wr2[1], sim2[1]);
                sim2[1] = fma2(wi2[1], sre2[1], m1);
                sre2[1] = t1;
                ull cc1 = fma2(cr2[1], sre2[1], mul2(nci2[1], sim2[1]));
                c2[j] = add2(cc0, cc1);
            }
            #pragma unroll
            for (int k = 4; k >= 1; k >>= 1) {
                bool hiq = (r & k) != 0;
                #pragma unroll
                for (int j = 0; j < k; j++) {
                    ull send = hiq ? c2[j]     : c2[j + k];
                    ull keep = hiq ? c2[j + k] : c2[j];
                    ull recv = __shfl_xor_sync(0xffffffffu, send, k);
                    c2[j] = add2(keep, recv);
                }
            }
            float lo_, hi_;
            upk2(c2[0], lo_, hi_);
            float y = lo_ + hi_;
            y = fmaf(ds, uv[q], y);
            y = 0.5f * y * (1.0f + erff(y * 0.70710678118654752f));
            bf16 yh = __float2bfloat16_rn(y);
            ghi[l0 + q * 8 + r] = yh;
            glo[l0 + q * 8 + r] = __float2bfloat16_rn(y - __bfloat162float(yh));
        }
    }
}

// ---------------- mma.sync bf16-split GEMM + fused GLU + residual(+prev-LN) ----------------
// K' = 1536: kt 0-7 Whi*Ghi, 8-15 Whi*Glo, 16-23 Wlo*Ghi.
// CTA tile M=128 (64 a-rows + 64 gate-rows) x N=128, BK=64; cp.async double buffer.
__global__ __launch_bounds__(256, 2) void gemm_mma_kernel(
        const bf16* __restrict__ whi, const bf16* __restrict__ wlo,
        const float* __restrict__ bias,
        const float* __restrict__ gam_prev, const float* __restrict__ bet_prev,
        int first) {
    extern __shared__ char smem[];
    const uint32_t sb = smem_u32(smem);
    const int tid = threadIdx.x;
    const int warp = tid >> 5, lane = tid & 31;
    const int wy = warp & 3, wx = warp >> 2;
    const int bN = blockIdx.x, bM = blockIdx.y, bb = blockIdx.z;
    const bf16* ghi = g_ghi + (size_t)bb * DM * LSEQ;
    const bf16* glo = g_glo + (size_t)bb * DM * LSEQ;

    float c[2][8][4];
    #pragma unroll
    for (int st = 0; st < 2; st++)
        #pragma unroll
        for (int nt = 0; nt < 8; nt++)
            #pragma unroll
            for (int j = 0; j < 4; j++) c[st][nt][j] = 0.0f;

    auto issue = [&](int kt, int s) {
        const bf16* Wsrc = (kt < 16) ? whi : wlo;
        const bf16* Gsrc = (kt >= 8 && kt < 16) ? glo : ghi;
        const int k0 = (kt & 7) * 64;
        const uint32_t As  = sb + s * 32768;
        const uint32_t Bsm = As + 16384;
        #pragma unroll
        for (int i = 0; i < 4; i++) {
            int ca = i * 256 + tid;                    // A: 1024 chunks (128m x 8)
            int m = ca >> 3, kc = ca & 7;
            int grow = (m < 64) ? (bM * 64 + m) : (448 + bM * 64 + m);
            cpasync16(As + m * 128 + ((kc ^ (m & 7)) << 4),
                      Wsrc + (size_t)grow * DM + k0 + kc * 8);
            int k = ca >> 4, cn = ca & 15;             // B: 1024 chunks (64k x 16)
            uint32_t cns = (cn & 8) | ((cn ^ (k & 7)) & 7);
            cpasync16(Bsm + k * 256 + (cns << 4),
                      Gsrc + (size_t)(k0 + k) * LSEQ + bN * 128 + cn * 8);
        }
        asm volatile("cp.async.commit_group;" ::: "memory");
    };

    issue(0, 0);
    const int q  = lane >> 3, r = lane & 7;
    const int qm = q & 1,  qh = q >> 1;
    const uint32_t aoff0 = (wy * 16 + qm * 8 + r) * 128;
    const uint32_t aoff1 = (64 + wy * 16 + qm * 8 + r) * 128;
    const uint32_t kboff = (qm * 8 + r) * 256;

    for (int kt = 0; kt < 24; kt++) {
        const int s = kt & 1;
        asm volatile("cp.async.wait_group 0;" ::: "memory");
        __syncthreads();
        if (kt < 23) issue(kt + 1, s ^ 1);
        const uint32_t As  = sb + s * 32768;
        const uint32_t Bsm = As + 16384;
        #pragma unroll
        for (int kk = 0; kk < 4; kk++) {
            uint32_t ac = (uint32_t)(((kk * 2 + qh) ^ r) << 4);
            uint32_t a0[4], a1[4];
            ldsm4(a0, As + aoff0 + ac);
            ldsm4(a1, As + aoff1 + ac);
            uint32_t bfr[4][4];
            uint32_t krow = Bsm + kboff + kk * 16 * 256;
            #pragma unroll
            for (int pt = 0; pt < 4; pt++) {
                uint32_t cn  = wx * 8 + pt * 2 + qh;
                uint32_t cns = (cn & 8) | ((cn ^ r) & 7);
                ldsm4t(bfr[pt], krow + (cns << 4));
            }
            #pragma unroll
            for (int nt = 0; nt < 8; nt++) {
                uint32_t b0 = bfr[nt >> 1][(nt & 1) * 2];
                uint32_t b1 = bfr[nt >> 1][(nt & 1) * 2 + 1];
                mma16816(c[0][nt], a0, b0, b1);
                mma16816(c[1][nt], a1, b0, b1);
            }
        }
    }

    // ---- epilogue: GLU + residual (+ prev-layer LN), registers only ----
    const int gi = lane >> 2, tig = lane & 3;
    const float* mb  = g_mean + (size_t)bb * LSEQ;
    const float* rb  = g_rstd + (size_t)bb * LSEQ;
    #pragma unroll
    for (int rr = 0; rr < 2; rr++) {                  // rows gi and gi+8
        int d = bM * 64 + wy * 16 + gi + rr * 8;
        float ba = bias[d];
        float bg = bias[512 + d];
        float gap = first ? 1.0f : gam_prev[d];
        float btp = first ? 0.0f : bet_prev[d];
        float pv  = first ? g_proj[bb * DM + d] : 0.0f;
        size_t rowbase = ((size_t)bb * DM + d) * LSEQ;
        const float* resrow = first ? (g_posT + (size_t)d * LSEQ) : (g_xp + rowbase);
        #pragma unroll
        for (int nt = 0; nt < 8; nt++) {
            int l = bN * 128 + wx * 64 + nt * 8 + 2 * tig;
            float av0 = c[0][nt][rr * 2]     + ba;
            float av1 = c[0][nt][rr * 2 + 1] + ba;
            float gv0 = c[1][nt][rr * 2]     + bg;
            float gv1 = c[1][nt][rr * 2 + 1] + bg;
            float2 xr = *(const float2*)&resrow[l];
            float x0, x1;
            if (first) { x0 = xr.x + pv; x1 = xr.y + pv; }
            else {
                float2 mn = *(const float2*)&mb[l];
                float2 rs = *(const float2*)&rb[l];
                x0 = fmaf((xr.x - mn.x) * rs.x, gap, btp);
                x1 = fmaf((xr.y - mn.y) * rs.y, gap, btp);
            }
            float o0 = fmaf(av0, 1.0f / (1.0f + expf(-gv0)), x0);
            float o1 = fmaf(av1, 1.0f / (1.0f + expf(-gv1)), x1);
            *(float2*)&g_xp[rowbase + l] = make_float2(o0, o1);
        }
    }
}

// ---------------- LN stats over xp (deterministic single pass) ----------------
__global__ void ln_stats_kernel() {
    int gid = blockIdx.x * 256 + threadIdx.x;        // 65536
    int b = gid >> 12, l = gid & (LSEQ - 1);
    const float* xp = g_xp + (size_t)b * DM * LSEQ + l;
    float s = 0.0f, s2 = 0.0f;
    #pragma unroll 8
    for (int d = 0; d < DM; d++) {
        float v = __ldg(&xp[(size_t)d * LSEQ]);
        s += v;
        s2 = fmaf(v, v, s2);
    }
    float mean = s * (1.0f / DM);
    float var  = fmaf(-mean, mean, s2 * (1.0f / DM));
    g_mean[gid] = mean;
    g_rstd[gid] = rsqrtf(var + 1e-5f);
}

// ---------------- pixel head (applies final LN inline) ----------------
// Output = concat(mu (B,3,H,W), log_sig (B,3,H,W)).
__global__ void pix_kernel(const float* __restrict__ Wpix,
                           const float* __restrict__ bpix,
                           const float* __restrict__ gam3,
                           const float* __restrict__ bet3,
                           float* __restrict__ out) {
    __shared__ float ws[6 * DM];
    __shared__ float gs[DM];
    __shared__ float bs[DM];
    for (int i = threadIdx.x; i < 6 * DM; i += 256) ws[i] = Wpix[i];
    for (int i = threadIdx.x; i < DM; i += 256) { gs[i] = gam3[i]; bs[i] = bet3[i]; }
    __syncthreads();
    int gid = blockIdx.x * 256 + threadIdx.x;        // 65536
    int b = gid >> 12, l = gid & (LSEQ - 1);
    const float* xb = g_xp + (size_t)b * DM * LSEQ + l;
    float mean = g_mean[gid];
    float rstd = g_rstd[gid];
    float acc[6];
    #pragma unroll
    for (int c = 0; c < 6; c++) acc[c] = __ldg(&bpix[c]);
    #pragma unroll 4
    for (int d = 0; d < DM; d++) {
        float v  = __ldg(&xb[(size_t)d * LSEQ]);
        float xv = fmaf((v - mean) * rstd, gs[d], bs[d]);
        #pragma unroll
        for (int c = 0; c < 6; c++) acc[c] = fmaf(xv, ws[c * DM + d], acc[c]);
    }
    const size_t halfsz = (size_t)NB * 3 * LSEQ;     // 196608
    #pragma unroll
    for (int c = 0; c < 6; c++) {
        size_t idx = (c < 3)
            ? ((size_t)(b * 3 + c) * LSEQ + l)
            : (halfsz + (size_t)(b * 3 + (c - 3)) * LSEQ + l);
        out[idx] = acc[c];
    }
}

// ---------------- launch ----------------
extern "C" void kernel_launch(void* const* d_in, const int* in_sizes, int n_in,
                              void* d_out, int out_size) {
    const float* z      = (const float*)d_in[0];
    const float* Wp     = (const float*)d_in[1];
    const float* bp     = (const float*)d_in[2];
    const float* pe     = (const float*)d_in[3];
    const float* log_dt = (const float*)d_in[4];
    const float* C_re   = (const float*)d_in[5];
    const float* C_im   = (const float*)d_in[6];
    const float* lar    = (const float*)d_in[7];
    const float* aim    = (const float*)d_in[8];
    const float* dsk    = (const float*)d_in[9];
    const float* Wconv  = (const float*)d_in[10];
    const float* bconv  = (const float*)d_in[11];
    const float* gam    = (const float*)d_in[12];
    const float* bet    = (const float*)d_in[13];
    const float* Wpix   = (const float*)d_in[14];
    const float* bpix   = (const float*)d_in[15];
    float* out = (float*)d_out;

    cudaFuncSetAttribute(gemm_mma_kernel, cudaFuncAttributeMaxDynamicSharedMemorySize, 65536);

    bf16* whi; cudaGetSymbolAddress((void**)&whi, g_whi);
    bf16* wlo; cudaGetSymbolAddress((void**)&wlo, g_wlo);

    initA_kernel<<<8192, 256>>>(log_dt, C_re, C_im, lar, aim, Wconv);   // launch 0
    initB_kernel<<<2080, 256>>>(pe, z, Wp, bp);                          // launch 1

    for (int l = 0; l < NL; l++) {
        const float* gp  = gam + (l > 0 ? (l - 1) : 0) * DM;
        const float* bp2 = bet + (l > 0 ? (l - 1) : 0) * DM;
        scan_kernel<<<256, 256>>>(dsk + l * DM, l, gp, bp2, l == 0);     // launch 2, 5, ...
        gemm_mma_kernel<<<dim3(32, 8, 16), 256, 65536>>>(                // launch 3 <- profiled
            whi + (size_t)l * 2 * DM * DM, wlo + (size_t)l * 2 * DM * DM,
            bconv + l * 2 * DM, gp, bp2, l == 0);
        ln_stats_kernel<<<256, 256>>>();
    }
    pix_kernel<<<256, 256>>>(Wpix, bpix, gam + 3 * DM, bet + 3 * DM, out);
}